// round 16
// baseline (speedup 1.0000x reference)
#include <cuda_runtime.h>
#include <cuda_bf16.h>

#define NUM_GRAPHS 256
#define EDGE_DIM   128
#define GLOBAL_DIM 256
#define LN_EPS     1e-5f

// Scratch (allocation-free rule: __device__ globals).
// Zero at module load; fuse_kernel re-zeros after use so graph replays stay clean.
__device__ float g_sums[NUM_GRAPHS * EDGE_DIM];
__device__ float g_counts[NUM_GRAPHS];

// One warp per contiguous chunk of ~423 edges. Lane l owns float4 columns [4l, 4l+4).
// Per segment-run inside the chunk: run end found in O(log chunk) broadcast loads
// (zero extra loads for single-segment chunks), then an unrolled streaming loop.
// Measured at 7.16 TB/s (~89% of HBM spec) — exact R7 form, frozen.
__global__ void __launch_bounds__(256) segsum_kernel(
    const float4* __restrict__ edge4,   // [n_edges, 32] float4
    const int* __restrict__ batch,      // [n_edges] int32, sorted
    int n_edges, int chunk)
{
    int warp  = (blockIdx.x * blockDim.x + threadIdx.x) >> 5;
    int lane  = threadIdx.x & 31;
    long long e0 = (long long)warp * chunk;
    long long e1 = e0 + chunk;
    if (e1 > n_edges) e1 = n_edges;
    if (e0 >= e1) return;

    int seg_last = batch[e1 - 1];

    long long e = e0;
    while (e < e1) {
        int seg = batch[e];
        long long end;
        if (seg == seg_last) {
            end = e1;                       // common case: rest of chunk is one run
        } else {
            long long lo = e, hi = e1 - 1;  // batch[lo]==seg, batch[hi]!=seg
            while (hi - lo > 1) {
                long long mid = (lo + hi) >> 1;
                if (batch[mid] == seg) lo = mid; else hi = mid;
            }
            end = hi;
        }

        float4 a0 = make_float4(0.f, 0.f, 0.f, 0.f);
        float4 a1 = make_float4(0.f, 0.f, 0.f, 0.f);
        const float4* p = edge4 + e * 32 + lane;
        long long n = end - e;
        long long i = 0;
        #pragma unroll 1
        for (; i + 8 <= n; i += 8) {
            float4 v0 = __ldcs(p + (i + 0) * 32);
            float4 v1 = __ldcs(p + (i + 1) * 32);
            float4 v2 = __ldcs(p + (i + 2) * 32);
            float4 v3 = __ldcs(p + (i + 3) * 32);
            float4 v4 = __ldcs(p + (i + 4) * 32);
            float4 v5 = __ldcs(p + (i + 5) * 32);
            float4 v6 = __ldcs(p + (i + 6) * 32);
            float4 v7 = __ldcs(p + (i + 7) * 32);
            a0.x += v0.x + v1.x + v2.x + v3.x;
            a0.y += v0.y + v1.y + v2.y + v3.y;
            a0.z += v0.z + v1.z + v2.z + v3.z;
            a0.w += v0.w + v1.w + v2.w + v3.w;
            a1.x += v4.x + v5.x + v6.x + v7.x;
            a1.y += v4.y + v5.y + v6.y + v7.y;
            a1.z += v4.z + v5.z + v6.z + v7.z;
            a1.w += v4.w + v5.w + v6.w + v7.w;
        }
        for (; i < n; i++) {
            float4 v = __ldcs(p + i * 32);
            a0.x += v.x; a0.y += v.y; a0.z += v.z; a0.w += v.w;
        }
        a0.x += a1.x; a0.y += a1.y; a0.z += a1.z; a0.w += a1.w;

        float* dst = &g_sums[seg * EDGE_DIM + lane * 4];
        atomicAdd(dst + 0, a0.x);
        atomicAdd(dst + 1, a0.y);
        atomicAdd(dst + 2, a0.z);
        atomicAdd(dst + 3, a0.w);
        if (lane == 0) atomicAdd(&g_counts[seg], (float)n);

        e = end;
    }
}

// One block (512 threads) per graph. 8-way k-split with float4 W loads:
// thread (q = t>>6, c4 = t&63) accumulates k in [16q, 16q+16) for columns
// [4*c4, 4*c4+4) — 16 independent LDG.128s into 4 accumulators. Scalar params
// (b, ln_w, ln_b, counts) hoisted before the first barrier so their loads
// overlap the g_sums epoch. Partials via smem, then two-pass LayerNorm.
// Also resets the scratch globals for the next graph replay.
__global__ void __launch_bounds__(512, 2) fuse_kernel(
    const float* __restrict__ W,    // [EDGE_DIM, GLOBAL_DIM]
    const float* __restrict__ b,    // [GLOBAL_DIM]
    const float* __restrict__ ln_w, // [GLOBAL_DIM]
    const float* __restrict__ ln_b, // [GLOBAL_DIM]
    float* __restrict__ out)        // [NUM_GRAPHS, GLOBAL_DIM]
{
    __shared__ float u_s[EDGE_DIM];
    __shared__ float part_s[8 * GLOBAL_DIM];   // 8 KB: [q][col]
    __shared__ float red[16];
    __shared__ float bc[2];

    int g = blockIdx.x;
    int t = threadIdx.x;
    int col = t & (GLOBAL_DIM - 1);

    // Hoisted scalar loads: issue before the barrier, consumed after the matmul.
    float bv   = b[col];
    float lnwv = ln_w[col];
    float lnbv = ln_b[col];

    if (t < EDGE_DIM) {
        float c = fmaxf(g_counts[g], 1.0f);
        u_s[t] = g_sums[g * EDGE_DIM + t] / c;
    }
    __syncthreads();

    // reset scratch for the next replay (after all reads above)
    if (t < EDGE_DIM) g_sums[g * EDGE_DIM + t] = 0.0f;
    if (t == 0)       g_counts[g] = 0.0f;

    int c4 = t & 63;   // float4 column group: cols [4*c4, 4*c4+4)
    int q  = t >> 6;   // k-group: k in [16q, 16q+16)

    const float4* W4 = (const float4*)W;        // [EDGE_DIM][64]
    const float4* wp = W4 + (q * 16) * 64 + c4;
    const float*  uq = u_s + q * 16;

    float4 acc = make_float4(0.f, 0.f, 0.f, 0.f);
    #pragma unroll
    for (int k = 0; k < 16; k++) {
        float4 w = wp[k * 64];
        float  u = uq[k];
        acc.x = fmaf(u, w.x, acc.x);
        acc.y = fmaf(u, w.y, acc.y);
        acc.z = fmaf(u, w.z, acc.z);
        acc.w = fmaf(u, w.w, acc.w);
    }
    // part_s[q][4*c4 .. 4*c4+3] = acc  (float4 store, conflict-free)
    ((float4*)part_s)[q * 64 + c4] = acc;
    __syncthreads();

    int half = t >> 8;           // 0 or 1
    float a = 0.0f;
    if (half == 0) {
        float s = bv;
        #pragma unroll
        for (int qq = 0; qq < 8; qq++)
            s += part_s[qq * GLOBAL_DIM + t];   // stride-256 across qq, conflict-free per warp
        a = s;
    }

    int wid = t >> 5, lane = t & 31;

    // pass 1: mean (upper half contributes zeros; divide by GLOBAL_DIM)
    float sum = a;
    #pragma unroll
    for (int o = 16; o; o >>= 1) sum += __shfl_xor_sync(0xffffffffu, sum, o);
    if (lane == 0) red[wid] = sum;
    __syncthreads();
    if (t == 0) {
        float S = 0.f;
        #pragma unroll
        for (int w = 0; w < 16; w++) S += red[w];
        bc[0] = S / (float)GLOBAL_DIM;
    }
    __syncthreads();
    float mu = bc[0];

    // pass 2: variance (guard upper half to contribute zero)
    float d  = a - mu;
    float sq = (half == 0) ? d * d : 0.0f;
    #pragma unroll
    for (int o = 16; o; o >>= 1) sq += __shfl_xor_sync(0xffffffffu, sq, o);
    if (lane == 0) red[wid] = sq;
    __syncthreads();
    if (t == 0) {
        float Q = 0.f;
        #pragma unroll
        for (int w = 0; w < 16; w++) Q += red[w];
        bc[1] = rsqrtf(Q / (float)GLOBAL_DIM + LN_EPS);
    }
    __syncthreads();
    float inv = bc[1];

    if (half == 0)
        out[g * GLOBAL_DIM + t] = d * inv * lnwv + lnbv;
}

extern "C" void kernel_launch(void* const* d_in, const int* in_sizes, int n_in,
                              void* d_out, int out_size) {
    const float* edge_attr = (const float*)d_in[0];
    const int*   batch     = (const int*)d_in[1];
    const float* W         = (const float*)d_in[2];
    const float* b         = (const float*)d_in[3];
    const float* ln_w      = (const float*)d_in[4];
    const float* ln_b      = (const float*)d_in[5];
    float*       out       = (float*)d_out;

    int n_edges = in_sizes[1];

    // Single wave: 4 CTAs/SM resident at any plausible register count.
    const int blocks = 592;                  // 148 SMs x 4 CTAs
    const int warps  = blocks * (256 / 32);  // 4736
    int chunk = (n_edges + warps - 1) / warps;
    if (chunk < 1) chunk = 1;
    segsum_kernel<<<blocks, 256>>>((const float4*)edge_attr, batch, n_edges, chunk);

    fuse_kernel<<<NUM_GRAPHS, 512>>>(W, b, ln_w, ln_b, out);
}

// round 17
// speedup vs baseline: 1.0037x; 1.0037x over previous
#include <cuda_runtime.h>
#include <cuda_bf16.h>

#define NUM_GRAPHS 256
#define EDGE_DIM   128
#define GLOBAL_DIM 256
#define LN_EPS     1e-5f

// Scratch (allocation-free rule: __device__ globals).
// Zero at module load; fuse_kernel re-zeros after use so graph replays stay clean.
__device__ float g_sums[NUM_GRAPHS * EDGE_DIM];
__device__ float g_counts[NUM_GRAPHS];

// One warp per contiguous chunk of ~423 edges. Lane l owns float4 columns [4l, 4l+4).
// Per segment-run inside the chunk: run end found in O(log chunk) broadcast loads
// (zero extra loads for single-segment chunks), then an unrolled streaming loop.
// Measured at 7.16 TB/s (~89% of HBM spec) — frozen.
__global__ void __launch_bounds__(256) segsum_kernel(
    const float4* __restrict__ edge4,   // [n_edges, 32] float4
    const int* __restrict__ batch,      // [n_edges] int32, sorted
    int n_edges, int chunk)
{
    int warp  = (blockIdx.x * blockDim.x + threadIdx.x) >> 5;
    int lane  = threadIdx.x & 31;
    long long e0 = (long long)warp * chunk;
    long long e1 = e0 + chunk;
    if (e1 > n_edges) e1 = n_edges;
    if (e0 >= e1) return;

    int seg_last = batch[e1 - 1];

    long long e = e0;
    while (e < e1) {
        int seg = batch[e];
        long long end;
        if (seg == seg_last) {
            end = e1;                       // common case: rest of chunk is one run
        } else {
            long long lo = e, hi = e1 - 1;  // batch[lo]==seg, batch[hi]!=seg
            while (hi - lo > 1) {
                long long mid = (lo + hi) >> 1;
                if (batch[mid] == seg) lo = mid; else hi = mid;
            }
            end = hi;
        }

        float4 a0 = make_float4(0.f, 0.f, 0.f, 0.f);
        float4 a1 = make_float4(0.f, 0.f, 0.f, 0.f);
        const float4* p = edge4 + e * 32 + lane;
        long long n = end - e;
        long long i = 0;
        #pragma unroll 1
        for (; i + 8 <= n; i += 8) {
            float4 v0 = __ldcs(p + (i + 0) * 32);
            float4 v1 = __ldcs(p + (i + 1) * 32);
            float4 v2 = __ldcs(p + (i + 2) * 32);
            float4 v3 = __ldcs(p + (i + 3) * 32);
            float4 v4 = __ldcs(p + (i + 4) * 32);
            float4 v5 = __ldcs(p + (i + 5) * 32);
            float4 v6 = __ldcs(p + (i + 6) * 32);
            float4 v7 = __ldcs(p + (i + 7) * 32);
            a0.x += v0.x + v1.x + v2.x + v3.x;
            a0.y += v0.y + v1.y + v2.y + v3.y;
            a0.z += v0.z + v1.z + v2.z + v3.z;
            a0.w += v0.w + v1.w + v2.w + v3.w;
            a1.x += v4.x + v5.x + v6.x + v7.x;
            a1.y += v4.y + v5.y + v6.y + v7.y;
            a1.z += v4.z + v5.z + v6.z + v7.z;
            a1.w += v4.w + v5.w + v6.w + v7.w;
        }
        for (; i < n; i++) {
            float4 v = __ldcs(p + i * 32);
            a0.x += v.x; a0.y += v.y; a0.z += v.z; a0.w += v.w;
        }
        a0.x += a1.x; a0.y += a1.y; a0.z += a1.z; a0.w += a1.w;

        float* dst = &g_sums[seg * EDGE_DIM + lane * 4];
        atomicAdd(dst + 0, a0.x);
        atomicAdd(dst + 1, a0.y);
        atomicAdd(dst + 2, a0.z);
        atomicAdd(dst + 3, a0.w);
        if (lane == 0) atomicAdd(&g_counts[seg], (float)n);

        e = end;
    }
}

// One block (512 threads) per graph. 8-way k-split with float4 W loads:
// thread (q = t>>6, c4 = t&63) accumulates k in [16q, 16q+16) for columns
// [4*c4, 4*c4+4) — 16 independent LDG.128s into 4 accumulators (high MLP,
// short chains). Partials combine through smem, then two-pass LayerNorm.
// Also resets the scratch globals for the next graph replay.
__global__ void __launch_bounds__(512, 2) fuse_kernel(
    const float* __restrict__ W,    // [EDGE_DIM, GLOBAL_DIM]
    const float* __restrict__ b,    // [GLOBAL_DIM]
    const float* __restrict__ ln_w, // [GLOBAL_DIM]
    const float* __restrict__ ln_b, // [GLOBAL_DIM]
    float* __restrict__ out)        // [NUM_GRAPHS, GLOBAL_DIM]
{
    __shared__ float u_s[EDGE_DIM];
    __shared__ float part_s[8 * GLOBAL_DIM];   // 8 KB: [q][col]
    __shared__ float red[16];
    __shared__ float bc[2];

    int g = blockIdx.x;
    int t = threadIdx.x;

    if (t < EDGE_DIM) {
        float c = fmaxf(g_counts[g], 1.0f);
        u_s[t] = g_sums[g * EDGE_DIM + t] / c;
    }
    __syncthreads();

    // reset scratch for the next replay (after all reads above)
    if (t < EDGE_DIM) g_sums[g * EDGE_DIM + t] = 0.0f;
    if (t == 0)       g_counts[g] = 0.0f;

    int c4 = t & 63;   // float4 column group: cols [4*c4, 4*c4+4)
    int q  = t >> 6;   // k-group: k in [16q, 16q+16)

    const float4* W4 = (const float4*)W;        // [EDGE_DIM][64]
    const float4* wp = W4 + (q * 16) * 64 + c4;
    const float*  uq = u_s + q * 16;

    float4 acc = make_float4(0.f, 0.f, 0.f, 0.f);
    #pragma unroll
    for (int k = 0; k < 16; k++) {
        float4 w = wp[k * 64];
        float  u = uq[k];
        acc.x = fmaf(u, w.x, acc.x);
        acc.y = fmaf(u, w.y, acc.y);
        acc.z = fmaf(u, w.z, acc.z);
        acc.w = fmaf(u, w.w, acc.w);
    }
    // part_s[q][4*c4 .. 4*c4+3] = acc  (float4 store, conflict-free)
    ((float4*)part_s)[q * 64 + c4] = acc;
    __syncthreads();

    int half = t >> 8;           // 0 or 1
    float a = 0.0f;
    if (half == 0) {
        float s = b[t];
        #pragma unroll
        for (int qq = 0; qq < 8; qq++)
            s += part_s[qq * GLOBAL_DIM + t];   // stride-256 across qq, conflict-free per warp
        a = s;
    }

    int wid = t >> 5, lane = t & 31;

    // pass 1: mean (upper half contributes zeros; divide by GLOBAL_DIM)
    float sum = a;
    #pragma unroll
    for (int o = 16; o; o >>= 1) sum += __shfl_xor_sync(0xffffffffu, sum, o);
    if (lane == 0) red[wid] = sum;
    __syncthreads();
    if (t == 0) {
        float S = 0.f;
        #pragma unroll
        for (int w = 0; w < 16; w++) S += red[w];
        bc[0] = S / (float)GLOBAL_DIM;
    }
    __syncthreads();
    float mu = bc[0];

    // pass 2: variance (guard upper half to contribute zero)
    float d  = a - mu;
    float sq = (half == 0) ? d * d : 0.0f;
    #pragma unroll
    for (int o = 16; o; o >>= 1) sq += __shfl_xor_sync(0xffffffffu, sq, o);
    if (lane == 0) red[wid] = sq;
    __syncthreads();
    if (t == 0) {
        float Q = 0.f;
        #pragma unroll
        for (int w = 0; w < 16; w++) Q += red[w];
        bc[1] = rsqrtf(Q / (float)GLOBAL_DIM + LN_EPS);
    }
    __syncthreads();
    float inv = bc[1];

    if (half == 0)
        out[g * GLOBAL_DIM + t] = d * inv * ln_w[t] + ln_b[t];
}

extern "C" void kernel_launch(void* const* d_in, const int* in_sizes, int n_in,
                              void* d_out, int out_size) {
    const float* edge_attr = (const float*)d_in[0];
    const int*   batch     = (const int*)d_in[1];
    const float* W         = (const float*)d_in[2];
    const float* b         = (const float*)d_in[3];
    const float* ln_w      = (const float*)d_in[4];
    const float* ln_b      = (const float*)d_in[5];
    float*       out       = (float*)d_out;

    int n_edges = in_sizes[1];

    // Single wave: 4 CTAs/SM resident at any plausible register count.
    const int blocks = 592;                  // 148 SMs x 4 CTAs
    const int warps  = blocks * (256 / 32);  // 4736
    int chunk = (n_edges + warps - 1) / warps;
    if (chunk < 1) chunk = 1;
    segsum_kernel<<<blocks, 256>>>((const float4*)edge_attr, batch, n_edges, chunk);

    fuse_kernel<<<NUM_GRAPHS, 512>>>(W, b, ln_w, ln_b, out);
}